// round 5
// baseline (speedup 1.0000x reference)
#include <cuda_runtime.h>
#include <cuda_bf16.h>

// Kuramoto–Sivashinsky explicit Euler, periodic BCs. dx=1, dt=0.01, NT=1000.
//   u' = u*(A0 + CN*(um1-up1)) + A1*(um1+up1) + A2*(um2+up2)
//   A2 = -dt*beta; A1 = dt*(4*beta - alpha); A0 = 1 + dt*(2*alpha - 6*beta); CN = 0.5*dt*c
//
// 64 CTAs (1/row) x 256 threads, 8 points/thread in four packed f32x2 regs.
// Per step: publish edge pairs to SMEM, compute the 2 interior chains BEFORE
// the barrier (hides barrier+skew), then LDS halos, compute the 2 edge chains,
// stream the 32B result to GMEM with st.global.cs. One __syncthreads per step,
// double-buffered SMEM, conflict-free u64 halo arrays.

#define KS_NT   1000
#define KS_NB   64
#define KS_NX   2048
#define KS_TPB  256   // 8 points per thread

typedef unsigned long long u64;

__device__ __forceinline__ u64 pk2(float lo, float hi) {
    u64 r; asm("mov.b64 %0, {%1, %2};" : "=l"(r) : "f"(lo), "f"(hi)); return r;
}
__device__ __forceinline__ float lo2(u64 v) {
    float a, b; asm("mov.b64 {%0, %1}, %2;" : "=f"(a), "=f"(b) : "l"(v)); return a;
}
__device__ __forceinline__ float hi2(u64 v) {
    float a, b; asm("mov.b64 {%0, %1}, %2;" : "=f"(a), "=f"(b) : "l"(v)); return b;
}
__device__ __forceinline__ u64 fadd2(u64 a, u64 b) {
    u64 r; asm("add.rn.f32x2 %0, %1, %2;" : "=l"(r) : "l"(a), "l"(b)); return r;
}
__device__ __forceinline__ u64 fmul2(u64 a, u64 b) {
    u64 r; asm("mul.rn.f32x2 %0, %1, %2;" : "=l"(r) : "l"(a), "l"(b)); return r;
}
__device__ __forceinline__ u64 ffma2(u64 a, u64 b, u64 c) {
    u64 r; asm("fma.rn.f32x2 %0, %1, %2, %3;" : "=l"(r) : "l"(a), "l"(b), "l"(c)); return r;
}
__device__ __forceinline__ void stcs128(float* p, u64 a, u64 b) {
    asm volatile("st.global.cs.v2.b64 [%0], {%1, %2};" :: "l"(p), "l"(a), "l"(b) : "memory");
}

struct KsConst { u64 A2p, A1p, A0p, CNp, N1p; };

// One pair update: points u (2 values), stencil pairs um2/um1/up1/up2.
__device__ __forceinline__ u64 ks_chain(u64 u, u64 um2, u64 um1, u64 up1, u64 up2,
                                        const KsConst& k)
{
    u64 s1  = fadd2(um1, up1);
    u64 s2  = fadd2(um2, up2);
    u64 d   = ffma2(up1, k.N1p, um1);        // um1 - up1
    u64 t   = ffma2(d, k.CNp, k.A0p);        // A0 + CN*d
    u64 acc = fmul2(u, t);                   // u*(A0 + CN*d)
    acc     = ffma2(s1, k.A1p, acc);
    return    ffma2(s2, k.A2p, acc);
}

__global__ void __launch_bounds__(KS_TPB, 1)
ks_kernel(const float* __restrict__ u0,
          const float* __restrict__ cptr,
          const float* __restrict__ aptr,
          const float* __restrict__ bptr,
          float* __restrict__ out)
{
    // double-buffered halo slots: L = thread's leftmost pair (p0,p1),
    // R = thread's rightmost pair (p6,p7). 8B stride -> conflict-free LDS.64.
    __shared__ u64 shL[2][KS_TPB];
    __shared__ u64 shR[2][KS_TPB];

    const int tid = threadIdx.x;
    const int row = blockIdx.x;

    const float cc    = *cptr;
    const float alpha = *aptr;
    const float beta  = *bptr;
    const float DTf   = 0.01f;

    const float A2 = -DTf * beta;
    const float A1 =  DTf * (4.0f * beta - alpha);
    const float A0 =  1.0f + DTf * (2.0f * alpha - 6.0f * beta);
    const float CN =  0.5f * DTf * cc;

    KsConst K;
    K.A2p = pk2(A2, A2);
    K.A1p = pk2(A1, A1);
    K.A0p = pk2(A0, A0);
    K.CNp = pk2(CN, CN);
    K.N1p = pk2(-1.0f, -1.0f);

    const size_t base = (size_t)row * KS_NX + ((size_t)tid << 3);

    // load initial state (32B) and emit step 0 = u0
    float4 ia = *(const float4*)(u0 + base);
    float4 ib = *(const float4*)(u0 + base + 4);
    *(float4*)(out + base)     = ia;
    *(float4*)(out + base + 4) = ib;

    u64 v0 = pk2(ia.x, ia.y);   // p0,p1
    u64 v1 = pk2(ia.z, ia.w);   // p2,p3
    u64 v2 = pk2(ib.x, ib.y);   // p4,p5
    u64 v3 = pk2(ib.z, ib.w);   // p6,p7

    float* outp = out + (size_t)KS_NB * KS_NX + base;   // step 1 slot
    const size_t ostride = (size_t)KS_NB * KS_NX;

    const int lidx = (tid - 1) & (KS_TPB - 1);
    const int ridx = (tid + 1) & (KS_TPB - 1);

    #pragma unroll 1
    for (int step = 0; step < KS_NT; step += 2) {
        #pragma unroll
        for (int half = 0; half < 2; ++half) {
            // publish edge pairs for this step
            shL[half][tid] = v0;
            shR[half][tid] = v3;

            // interior composed (shifted) pairs — no halo needed
            const u64 c12 = pk2(hi2(v0), lo2(v1));   // (p1,p2)
            const u64 c34 = pk2(hi2(v1), lo2(v2));   // (p3,p4)
            const u64 c56 = pk2(hi2(v2), lo2(v3));   // (p5,p6)

            // interior chains BEFORE the barrier (hides barrier skew/latency)
            const u64 nv1 = ks_chain(v1, v0, c12, c34, v2, K);  // p2,p3
            const u64 nv2 = ks_chain(v2, v1, c34, c56, v3, K);  // p4,p5

            __syncthreads();

            const u64 hl = shR[half][lidx];   // (p-2, p-1)
            const u64 hr = shL[half][ridx];   // (p8,  p9)

            const u64 m01 = pk2(hi2(hl), lo2(v0));   // (p-1, p0)
            const u64 p78 = pk2(hi2(v3), lo2(hr));   // (p7,  p8)

            const u64 nv0 = ks_chain(v0, hl, m01, c12, v1, K);  // p0,p1
            const u64 nv3 = ks_chain(v3, v2, c56, p78, hr, K);  // p6,p7

            // streaming stores: 32B per thread per step
            stcs128(outp,     nv0, nv1);
            stcs128(outp + 4, nv2, nv3);
            outp += ostride;

            v0 = nv0; v1 = nv1; v2 = nv2; v3 = nv3;
        }
    }
}

extern "C" void kernel_launch(void* const* d_in, const int* in_sizes, int n_in,
                              void* d_out, int out_size)
{
    (void)in_sizes; (void)n_in; (void)out_size;
    const float* u0    = (const float*)d_in[0];
    const float* c     = (const float*)d_in[1];
    const float* alpha = (const float*)d_in[2];
    const float* beta  = (const float*)d_in[3];
    ks_kernel<<<KS_NB, KS_TPB>>>(u0, c, alpha, beta, (float*)d_out);
}

// round 6
// speedup vs baseline: 1.1502x; 1.1502x over previous
#include <cuda_runtime.h>
#include <cuda_bf16.h>
#include <cstdint>

// Kuramoto–Sivashinsky explicit Euler, periodic, dx=1, dt=0.01, NT=1000.
//   u' = u*A0 + (um1+up1)*A1 + (um2+up2)*A2 + u*CN*(um1-up1)
//   A0 = 1+dt(2a-6b); A1 = dt(4b-a); A2 = -dt*b; CN = dt*c/2
//
// 128 CTAs = 64 rows x cluster-of-2. Each CTA owns 1024 points (512 thr x 1
// f32x2 pair) plus 8 ghost pairs per side, redundantly advanced so cross-CTA
// DSMEM exchange is needed only every 8 steps (ghost shrinks 1 pair/side/step).
// Exchange: 16 edge threads st.shared::cluster their fresh edge pairs into the
// peer's recv buffer + release-arrive on peer mbarrier; consumer acquire-waits
// at block start. Intra-CTA halo: double-buffered SMEM + 1 __syncthreads/step.
// All math is fma.rn.f32x2 (FFMA2) — 7 per pair.

#define KS_NT    1000
#define KS_NB    64
#define KS_NX    2048
#define KS_TPB   512
#define KS_HALF  1024
#define KS_GP    8                    // ghost pairs per side
#define KS_KB    8                    // steps per exchange block
#define KS_NBLK  (KS_NT / KS_KB)      // 125
#define SLOTS    (KS_TPB + 2*KS_GP)   // 528 pair slots: [0..7]=gL [8..519]=own [520..527]=gR

typedef unsigned long long u64;

__device__ __forceinline__ u64 pk2(float lo, float hi) {
    u64 r; asm("mov.b64 %0, {%1, %2};" : "=l"(r) : "f"(lo), "f"(hi)); return r;
}
__device__ __forceinline__ float lo2(u64 v) {
    float a, b; asm("mov.b64 {%0, %1}, %2;" : "=f"(a), "=f"(b) : "l"(v)); return a;
}
__device__ __forceinline__ float hi2(u64 v) {
    float a, b; asm("mov.b64 {%0, %1}, %2;" : "=f"(a), "=f"(b) : "l"(v)); return b;
}
__device__ __forceinline__ u64 ffma2(u64 a, u64 b, u64 c) {
    u64 r; asm("fma.rn.f32x2 %0, %1, %2, %3;" : "=l"(r) : "l"(a), "l"(b), "l"(c)); return r;
}

__device__ __forceinline__ uint32_t smem_u32(const void* p) {
    uint32_t a; asm("{ .reg .u64 t; cvta.to.shared.u64 t, %1; cvt.u32.u64 %0, t; }"
                    : "=r"(a) : "l"(p));
    return a;
}
__device__ __forceinline__ uint32_t mapa32(uint32_t local, uint32_t rank) {
    uint32_t r; asm("mapa.shared::cluster.u32 %0, %1, %2;" : "=r"(r) : "r"(local), "r"(rank));
    return r;
}
__device__ __forceinline__ void st_cluster64(uint32_t addr, u64 v) {
    asm volatile("st.shared::cluster.b64 [%0], %1;" :: "r"(addr), "l"(v) : "memory");
}
__device__ __forceinline__ void arrive_cluster(uint32_t remote_mbar) {
    asm volatile("mbarrier.arrive.release.cluster.shared::cluster.b64 _, [%0];"
                 :: "r"(remote_mbar) : "memory");
}
__device__ __forceinline__ void wait_parity_cluster(uint32_t mbar, uint32_t phase) {
    uint32_t done;
    asm volatile(
        "{\n\t.reg .pred p;\n\t"
        "mbarrier.try_wait.parity.acquire.cluster.shared::cta.b64 p, [%1], %2;\n\t"
        "selp.b32 %0, 1, 0, p;\n\t}"
        : "=r"(done) : "r"(mbar), "r"(phase) : "memory");
    if (!done) {
        asm volatile(
            "{\n\t.reg .pred P1;\n\t"
            "WL_%=:\n\t"
            "mbarrier.try_wait.parity.acquire.cluster.shared::cta.b64 P1, [%0], %1, 0x989680;\n\t"
            "@P1 bra.uni WD_%=;\n\t"
            "bra.uni WL_%=;\n\t"
            "WD_%=:\n\t}"
            :: "r"(mbar), "r"(phase) : "memory");
    }
}

struct KsK { u64 A0, A1, A2, CN, ONE, NEG1, ZERO; };

// One pair update via 7 dependent-free-mixed FFMA2.
__device__ __forceinline__ u64 ks7(u64 u, u64 um1, u64 up1, u64 um2, u64 up2, const KsK& k)
{
    u64 s1 = ffma2(um1, k.ONE,  up1);   // um1+up1
    u64 s2 = ffma2(um2, k.ONE,  up2);   // um2+up2
    u64 d  = ffma2(up1, k.NEG1, um1);   // um1-up1
    u64 t  = ffma2(d,   k.CN,   k.A0);  // A0 + CN*d
    u64 r  = ffma2(u,   t,      k.ZERO);
    r      = ffma2(s1,  k.A1,   r);
    return   ffma2(s2,  k.A2,   r);
}

__global__ void __launch_bounds__(KS_TPB, 1) __cluster_dims__(2, 1, 1)
ks_kernel(const float* __restrict__ u0,
          const float* __restrict__ cptr,
          const float* __restrict__ aptr,
          const float* __restrict__ bptr,
          float* __restrict__ out)
{
    __shared__ u64 sh[2][SLOTS];         // double-buffered per-step halo (pairs)
    __shared__ u64 recvL[2][KS_GP];      // block-parity recv: peer's right-edge pairs
    __shared__ u64 recvR[2][KS_GP];      // block-parity recv: peer's left-edge pairs
    __shared__ u64 mbar[2];

    const int t    = threadIdx.x;
    const int row  = blockIdx.x >> 1;
    const int rank = blockIdx.x & 1;
    const int peer = rank ^ 1;
    const int start = rank * KS_HALF;

    // ── constants ──
    const float cc = *cptr, alpha = *aptr, beta = *bptr, DTf = 0.01f;
    KsK K;
    {
        const float A0 = 1.0f + DTf * (2.0f * alpha - 6.0f * beta);
        const float A1 = DTf * (4.0f * beta - alpha);
        const float A2 = -DTf * beta;
        const float CN = 0.5f * DTf * cc;
        K.A0 = pk2(A0, A0); K.A1 = pk2(A1, A1); K.A2 = pk2(A2, A2);
        K.CN = pk2(CN, CN); K.ONE = pk2(1.0f, 1.0f);
        K.NEG1 = pk2(-1.0f, -1.0f); K.ZERO = pk2(0.0f, 0.0f);
    }

    // ── mbarrier init + cluster handshake ──
    const uint32_t mbar_base = smem_u32(&mbar[0]);
    if (t == 0) {
        asm volatile("mbarrier.init.shared.b64 [%0], %1;" :: "r"(mbar_base),     "r"(16) : "memory");
        asm volatile("mbarrier.init.shared.b64 [%0], %1;" :: "r"(mbar_base + 8), "r"(16) : "memory");
    }
    __syncthreads();
    asm volatile("barrier.cluster.arrive.aligned;" ::: "memory");
    asm volatile("barrier.cluster.wait.aligned;"   ::: "memory");

    // ── roles ──
    const bool ghosty = (t < 16);                         // warp 0 lanes 0..15 own ghosts
    const int  gs = (t < 8) ? t : (512 + t);              // ghost slot: 0..7 or 520..527
    const int  gl = (gs == 0) ? 0 : gs - 1;
    const int  gr = (gs == SLOTS - 1) ? SLOTS - 1 : gs + 1;

    // producers: t<8 send own pair -> peer recvR[t]; t>=504 send -> peer recvL[t-504]
    uint32_t remSlot0 = 0, remSlot1 = 0;
    const bool prodLo = (t < 8), prodHi = (t >= KS_TPB - 8);
    if (prodLo) {
        remSlot0 = mapa32(smem_u32(&recvR[0][t]), peer);
        remSlot1 = mapa32(smem_u32(&recvR[1][t]), peer);
    } else if (prodHi) {
        remSlot0 = mapa32(smem_u32(&recvL[0][t - (KS_TPB - 8)]), peer);
        remSlot1 = mapa32(smem_u32(&recvL[1][t - (KS_TPB - 8)]), peer);
    }
    const uint32_t remMbar0 = mapa32(mbar_base,     peer);
    const uint32_t remMbar1 = mapa32(mbar_base + 8, peer);
    const uint32_t locMbar0 = mbar_base, locMbar1 = mbar_base + 8;

    // ── initial state ──
    const float* urow = u0 + (size_t)row * KS_NX;
    u64 v = pk2(urow[start + 2 * t], urow[start + 2 * t + 1]);

    u64 g = 0;
    if (ghosty) {
        int gpt;
        if (t < 8) gpt = (start - 2 * KS_GP + 2 * t + KS_NX) & (KS_NX - 1);     // left ghosts
        else       gpt = (start + KS_HALF + 2 * (t - 8)) & (KS_NX - 1);         // right ghosts
        g = pk2(urow[gpt], urow[gpt + 1]);
    }

    // emit step 0 = u0 (own points only)
    float* outp = out + (size_t)row * KS_NX + start + 2 * t;
    *(u64*)outp = v;
    const size_t ostride = (size_t)KS_NB * KS_NX;
    outp += ostride;                                       // step 1 slot

    uint32_t ph0 = 0, ph1 = 0;                             // consumer phase per mbar

    // ── main: 125 blocks x 8 steps ──
    #pragma unroll 1
    for (int b = 0; b < KS_NBLK; ++b) {
        if (ghosty && b > 0) {
            const int bi = b & 1;
            if (bi) { wait_parity_cluster(locMbar1, ph1); ph1 ^= 1; }
            else    { wait_parity_cluster(locMbar0, ph0); ph0 ^= 1; }
            g = (t < 8) ? recvL[bi][t] : recvR[bi][t - 8];
        }

        #pragma unroll
        for (int s = 0; s < KS_KB; ++s) {
            const int sp = s & 1;

            sh[sp][KS_GP + t] = v;
            if (ghosty) sh[sp][gs] = g;
            __syncthreads();

            const u64 L = sh[sp][KS_GP + t - 1];
            const u64 R = sh[sp][KS_GP + t + 1];
            const u64 um1 = pk2(hi2(L), lo2(v));
            const u64 up1 = pk2(hi2(v), lo2(R));
            const u64 nv = ks7(v, um1, up1, L, R, K);

            if (ghosty) {
                const u64 Lg = sh[sp][gl];
                const u64 Rg = sh[sp][gr];
                const u64 gum1 = pk2(hi2(Lg), lo2(g));
                const u64 gup1 = pk2(hi2(g), lo2(Rg));
                g = ks7(g, gum1, gup1, Lg, Rg, K);
            }

            v = nv;
            *(u64*)outp = v;                               // 8B coalesced store
            outp += ostride;

            if (s == KS_KB - 1 && b < KS_NBLK - 1 && (prodLo || prodHi)) {
                if ((b + 1) & 1) { st_cluster64(remSlot1, v); arrive_cluster(remMbar1); }
                else             { st_cluster64(remSlot0, v); arrive_cluster(remMbar0); }
            }
        }
    }

    // no CTA exits while peer traffic could target it
    asm volatile("barrier.cluster.arrive.aligned;" ::: "memory");
    asm volatile("barrier.cluster.wait.aligned;"   ::: "memory");
}

extern "C" void kernel_launch(void* const* d_in, const int* in_sizes, int n_in,
                              void* d_out, int out_size)
{
    (void)in_sizes; (void)n_in; (void)out_size;
    const float* u0    = (const float*)d_in[0];
    const float* c     = (const float*)d_in[1];
    const float* alpha = (const float*)d_in[2];
    const float* beta  = (const float*)d_in[3];
    ks_kernel<<<KS_NB * 2, KS_TPB>>>(u0, c, alpha, beta, (float*)d_out);
}